// round 1
// baseline (speedup 1.0000x reference)
#include <cuda_runtime.h>

// GCN_56882546868697 — 2-layer GCN forward on GB300 (sm_103a)
// Inputs (metadata order): nodes[f32 N*64], senders[i32 E], receivers[i32 E],
//                          W0[f32 64*64], b0[f32 64], W1[f32 64*16], b1[f32 16]
// Output: out[f32 N*16]

#define NN 100000
#define NE 1600000
#define DF 64
#define LT 64
#define NC 16
#define NEG_SLOPE 0.01f

// Scratch (static __device__ — no runtime allocation allowed)
__device__ float g_h [NN * LT];   // layer-1 pre-aggregation (scaled)
__device__ float g_h2[NN * LT];   // layer-1 aggregated
__device__ float g_z [NN * NC];   // layer-2 activations (sigmoid)
__device__ float g_deg_s[NN];
__device__ float g_deg_r[NN];

// ---------------------------------------------------------------- zero
__global__ void k_zero(float* __restrict__ out, int n_out) {
    const int stride = gridDim.x * blockDim.x;
    const int t0 = blockIdx.x * blockDim.x + threadIdx.x;
    for (int i = t0; i < NN * LT; i += stride) g_h2[i] = 0.0f;
    for (int i = t0; i < NN; i += stride) { g_deg_s[i] = 0.0f; g_deg_r[i] = 0.0f; }
    for (int i = t0; i < n_out; i += stride) out[i] = 0.0f;
}

// ---------------------------------------------------------------- degrees
__global__ void k_degrees(const int* __restrict__ senders,
                          const int* __restrict__ receivers, int ne) {
    int e = blockIdx.x * blockDim.x + threadIdx.x;
    if (e < ne) {
        atomicAdd(&g_deg_s[__ldg(&senders[e])], 1.0f);
        atomicAdd(&g_deg_r[__ldg(&receivers[e])], 1.0f);
    }
}

// ---------------------------------------------------------------- GEMM1 + sender-norm
// h[n, :] = (nodes[n, :] @ W0 + b0) * rsqrt(max(deg_s[n],1))
// block = 256 threads = 4 rows x 64 cols; W0 staged in smem (16KB)
__global__ void k_gemm1(const float* __restrict__ nodes,
                        const float* __restrict__ W0,
                        const float* __restrict__ b0, int nn) {
    __shared__ float sW[DF * LT];
    __shared__ float sx[4][DF];
    const int tid = threadIdx.x;
    for (int i = tid; i < DF * LT; i += 256) sW[i] = W0[i];

    const int r = tid >> 6;        // 0..3
    const int c = tid & 63;        // 0..63
    const int row0 = blockIdx.x * 4;
    const int row = row0 + r;
    if (row < nn) sx[r][c] = nodes[row * DF + c];
    __syncthreads();

    if (row >= nn) return;
    float acc = __ldg(&b0[c]);
#pragma unroll
    for (int k = 0; k < DF; ++k) acc += sx[r][k] * sW[k * LT + c];
    const float s = rsqrtf(fmaxf(g_deg_s[row], 1.0f));
    g_h[row * LT + c] = acc * s;
}

// ---------------------------------------------------------------- scatter layer 1
// h2[recv] += h[send]  — one thread per (edge, 16B chunk), vector RED to L2
__global__ void k_scatter1(const int* __restrict__ senders,
                           const int* __restrict__ receivers, int ne) {
    const int t = blockIdx.x * blockDim.x + threadIdx.x;
    const int e = t >> 4;          // edge
    const int c = t & 15;          // chunk of 4 floats
    if (e >= ne) return;
    const int s = __ldg(&senders[e]);
    const int r = __ldg(&receivers[e]);
    const float4 v = *reinterpret_cast<const float4*>(&g_h[s * LT + c * 4]);
    float* dst = &g_h2[r * LT + c * 4];
    asm volatile("red.global.add.v4.f32 [%0], {%1, %2, %3, %4};"
                 :: "l"(dst), "f"(v.x), "f"(v.y), "f"(v.z), "f"(v.w)
                 : "memory");
}

// ---------------------------------------------------------------- receiver-norm + leaky + GEMM2 + sigmoid
// z[n, :] = sigmoid( leaky(h2[n,:] * rsqrt(max(deg_r,1))) @ W1 + b1 )
// block = 256 threads = 16 rows x 16 cols
__global__ void k_layer2(const float* __restrict__ W1,
                         const float* __restrict__ b1, int nn) {
    __shared__ float sW1[LT * NC];       // 4KB, [k][c]
    __shared__ float sact[16][LT + 1];   // +1 pad: avoid 2-way bank conflict
    const int tid = threadIdx.x;
    for (int i = tid; i < LT * NC; i += 256) sW1[i] = W1[i];

    const int lr = tid >> 4;       // 0..15 local row
    const int c  = tid & 15;       // 0..15 out col
    const int row = blockIdx.x * 16 + lr;

    if (row < nn) {
        const float dr = rsqrtf(fmaxf(g_deg_r[row], 1.0f));
#pragma unroll
        for (int j = 0; j < 4; ++j) {
            float v = g_h2[row * LT + c * 4 + j] * dr;
            v = (v >= 0.0f) ? v : NEG_SLOPE * v;
            sact[lr][c * 4 + j] = v;
        }
    }
    __syncthreads();
    if (row >= nn) return;

    float acc = __ldg(&b1[c]);
#pragma unroll
    for (int k = 0; k < LT; ++k) acc += sact[lr][k] * sW1[k * NC + c];
    g_z[row * NC + c] = 1.0f / (1.0f + __expf(-acc));
}

// ---------------------------------------------------------------- scatter layer 2
// out[recv] += z[send] — one thread per (edge, 16B chunk)
__global__ void k_scatter2(const int* __restrict__ senders,
                           const int* __restrict__ receivers,
                           float* __restrict__ out, int ne) {
    const int t = blockIdx.x * blockDim.x + threadIdx.x;
    const int e = t >> 2;          // edge
    const int c = t & 3;           // chunk of 4 floats
    if (e >= ne) return;
    const int s = __ldg(&senders[e]);
    const int r = __ldg(&receivers[e]);
    const float4 v = *reinterpret_cast<const float4*>(&g_z[s * NC + c * 4]);
    float* dst = &out[r * NC + c * 4];
    asm volatile("red.global.add.v4.f32 [%0], {%1, %2, %3, %4};"
                 :: "l"(dst), "f"(v.x), "f"(v.y), "f"(v.z), "f"(v.w)
                 : "memory");
}

// ---------------------------------------------------------------- launch
extern "C" void kernel_launch(void* const* d_in, const int* in_sizes, int n_in,
                              void* d_out, int out_size) {
    const float* nodes     = (const float*)d_in[0];
    const int*   senders   = (const int*)  d_in[1];
    const int*   receivers = (const int*)  d_in[2];
    const float* W0        = (const float*)d_in[3];
    const float* b0        = (const float*)d_in[4];
    const float* W1        = (const float*)d_in[5];
    const float* b1        = (const float*)d_in[6];
    float*       out       = (float*)d_out;

    const int nn = in_sizes[0] / DF;   // 100000
    const int ne = in_sizes[1];        // 1600000

    k_zero<<<1024, 256>>>(out, out_size);
    k_degrees<<<(ne + 255) / 256, 256>>>(senders, receivers, ne);
    k_gemm1<<<(nn + 3) / 4, 256>>>(nodes, W0, b0, nn);
    {
        long long work = (long long)ne * 16;
        k_scatter1<<<(int)((work + 255) / 256), 256>>>(senders, receivers, ne);
    }
    k_layer2<<<(nn + 15) / 16, 256>>>(W1, b1, nn);
    {
        long long work = (long long)ne * 4;
        k_scatter2<<<(int)((work + 255) / 256), 256>>>(senders, receivers, out, ne);
    }
}

// round 2
// speedup vs baseline: 1.8254x; 1.8254x over previous
#include <cuda_runtime.h>

// GCN_56882546868697 — 2-layer GCN, CSR pull-aggregation version (GB300 sm_103a)
// Inputs: nodes[f32 N*64], senders[i32 E], receivers[i32 E],
//         W0[f32 64*64], b0[f32 64], W1[f32 64*16], b1[f32 16]
// Output: out[f32 N*16]

#define NN 100000
#define NE 1600000
#define DF 64
#define LT 64
#define NC 16
#define NEG 0.01f

// ---- static scratch (no runtime allocation allowed) ----
__device__ __align__(16) float g_h[NN * LT];   // layer-1 pre-agg (scaled by sender norm)
__device__ __align__(16) float g_z[NN * NC];   // layer-2 sigmoid activations
__device__ int g_degs[NN];                     // out-degree (sender)
__device__ int g_degr[NN];                     // in-degree (receiver)
__device__ int g_row[NN + 1];                  // CSR row offsets (by receiver)
__device__ int g_cur[NN];                      // binning cursors
__device__ int g_csr[NE];                      // sender list grouped by receiver
__device__ int g_part[512];                    // scan partials

// ---------------------------------------------------------------- init
__global__ void k_init(int nn) {
    const int stride = gridDim.x * blockDim.x;
    for (int i = blockIdx.x * blockDim.x + threadIdx.x; i < nn; i += stride) {
        g_degs[i] = 0; g_degr[i] = 0;
    }
}

// ---------------------------------------------------------------- degree histograms
__global__ void k_degrees(const int* __restrict__ senders,
                          const int* __restrict__ receivers, int ne) {
    int e = blockIdx.x * blockDim.x + threadIdx.x;
    if (e < ne) {
        atomicAdd(&g_degs[__ldg(&senders[e])], 1);
        atomicAdd(&g_degr[__ldg(&receivers[e])], 1);
    }
}

// ---------------------------------------------------------------- scan (3 kernels)
__global__ void k_scan1(int nn) {   // per-block sums of g_degr
    __shared__ int s[256];
    int i = blockIdx.x * 256 + threadIdx.x;
    s[threadIdx.x] = (i < nn) ? g_degr[i] : 0;
    __syncthreads();
    for (int o = 128; o > 0; o >>= 1) {
        if (threadIdx.x < o) s[threadIdx.x] += s[threadIdx.x + o];
        __syncthreads();
    }
    if (threadIdx.x == 0) g_part[blockIdx.x] = s[0];
}

__global__ void k_scan2(int nb) {   // exclusive scan of <=512 partials, 1 block
    __shared__ int s[512];
    int tid = threadIdx.x;
    int v = (tid < nb) ? g_part[tid] : 0;
    s[tid] = v;
    __syncthreads();
    for (int o = 1; o < 512; o <<= 1) {
        int t = (tid >= o) ? s[tid - o] : 0;
        __syncthreads();
        s[tid] += t;
        __syncthreads();
    }
    g_part[tid] = s[tid] - v;   // exclusive
}

__global__ void k_scan3(int nn) {   // write row offsets + cursors
    __shared__ int s[256];
    int tid = threadIdx.x;
    int i = blockIdx.x * 256 + tid;
    int v = (i < nn) ? g_degr[i] : 0;
    s[tid] = v;
    __syncthreads();
    for (int o = 1; o < 256; o <<= 1) {
        int t = (tid >= o) ? s[tid - o] : 0;
        __syncthreads();
        s[tid] += t;
        __syncthreads();
    }
    int excl = s[tid] - v;
    int base = g_part[blockIdx.x];
    if (i < nn) {
        int r = base + excl;
        g_row[i] = r;
        g_cur[i] = r;
        if (i == nn - 1) g_row[nn] = r + v;
    }
}

// ---------------------------------------------------------------- bin edges by receiver
__global__ void k_bin(const int* __restrict__ senders,
                      const int* __restrict__ receivers, int ne) {
    int e = blockIdx.x * blockDim.x + threadIdx.x;
    if (e < ne) {
        int r = __ldg(&receivers[e]);
        int p = atomicAdd(&g_cur[r], 1);
        g_csr[p] = __ldg(&senders[e]);
    }
}

// ---------------------------------------------------------------- GEMM1 + sender norm
// 64x64 output tile per block; 256 threads, each a 4x4 register tile.
__global__ void k_gemm1(const float* __restrict__ nodes,
                        const float* __restrict__ W0,
                        const float* __restrict__ b0, int nn) {
    __shared__ __align__(16) float sW[DF * LT];      // [k][c]
    __shared__ float sx[64][DF + 1];                 // [r][k]
    const int tid = threadIdx.x;
    const int row0 = blockIdx.x * 64;

    for (int i = tid; i < DF * LT; i += 256) sW[i] = W0[i];
    for (int idx = tid; idx < 64 * 16; idx += 256) {
        int r = idx >> 4, k0 = (idx & 15) * 4;
        int grow = row0 + r;
        float4 v = (grow < nn)
            ? *reinterpret_cast<const float4*>(&nodes[grow * DF + k0])
            : make_float4(0.f, 0.f, 0.f, 0.f);
        sx[r][k0] = v.x; sx[r][k0 + 1] = v.y; sx[r][k0 + 2] = v.z; sx[r][k0 + 3] = v.w;
    }
    __syncthreads();

    const int ty = tid >> 4, tx = tid & 15;
    const int r0 = ty * 4, c0 = tx * 4;
    float acc[4][4] = {};
#pragma unroll
    for (int k = 0; k < DF; ++k) {
        float4 b = *reinterpret_cast<const float4*>(&sW[k * LT + c0]);
        float a0 = sx[r0][k], a1 = sx[r0 + 1][k], a2 = sx[r0 + 2][k], a3 = sx[r0 + 3][k];
        acc[0][0] += a0 * b.x; acc[0][1] += a0 * b.y; acc[0][2] += a0 * b.z; acc[0][3] += a0 * b.w;
        acc[1][0] += a1 * b.x; acc[1][1] += a1 * b.y; acc[1][2] += a1 * b.z; acc[1][3] += a1 * b.w;
        acc[2][0] += a2 * b.x; acc[2][1] += a2 * b.y; acc[2][2] += a2 * b.z; acc[2][3] += a2 * b.w;
        acc[3][0] += a3 * b.x; acc[3][1] += a3 * b.y; acc[3][2] += a3 * b.z; acc[3][3] += a3 * b.w;
    }
    const float4 bias = *reinterpret_cast<const float4*>(&b0[c0]);
#pragma unroll
    for (int i = 0; i < 4; ++i) {
        int grow = row0 + r0 + i;
        if (grow < nn) {
            float s = rsqrtf(fmaxf((float)g_degs[grow], 1.0f));
            float4 o;
            o.x = (acc[i][0] + bias.x) * s;
            o.y = (acc[i][1] + bias.y) * s;
            o.z = (acc[i][2] + bias.z) * s;
            o.w = (acc[i][3] + bias.w) * s;
            *reinterpret_cast<float4*>(&g_h[grow * LT + c0]) = o;
        }
    }
}

// ---------------------------------------------------------------- agg1 + norm + leaky + GEMM2 + sigmoid
// 256 threads = 16 nodes x 16 lanes. Phase A: pull-aggregate h over CSR
// (each lane owns a float4 column chunk), normalize + leaky, stage to smem.
// Phase B: 16x16 GEMM2 from smem + sigmoid -> g_z.
__global__ void k_agg1l2(const float* __restrict__ W1,
                         const float* __restrict__ b1, int nn) {
    __shared__ float sW1[LT * NC];          // [k][c]
    __shared__ float sact[16][LT + 1];
    const int tid = threadIdx.x;
    for (int i = tid; i < LT * NC; i += 256) sW1[i] = W1[i];

    const int ln = tid >> 4;        // node within block
    const int c  = tid & 15;        // float4 chunk
    const int node = blockIdx.x * 16 + ln;

    if (node < nn) {
        int beg = g_row[node], end = g_row[node + 1];
        float ax = 0.f, ay = 0.f, az = 0.f, aw = 0.f;
        for (int i = beg; i < end; ++i) {
            int s = g_csr[i];
            float4 v = *reinterpret_cast<const float4*>(&g_h[s * LT + c * 4]);
            ax += v.x; ay += v.y; az += v.z; aw += v.w;
        }
        float dr = rsqrtf(fmaxf((float)(end - beg), 1.0f));
        ax *= dr; ay *= dr; az *= dr; aw *= dr;
        ax = (ax >= 0.f) ? ax : NEG * ax;
        ay = (ay >= 0.f) ? ay : NEG * ay;
        az = (az >= 0.f) ? az : NEG * az;
        aw = (aw >= 0.f) ? aw : NEG * aw;
        sact[ln][c * 4 + 0] = ax;
        sact[ln][c * 4 + 1] = ay;
        sact[ln][c * 4 + 2] = az;
        sact[ln][c * 4 + 3] = aw;
    }
    __syncthreads();

    if (node >= nn) return;         // same (ln,c) decomposition reused as (row, outcol)
    float acc = __ldg(&b1[c]);
#pragma unroll
    for (int k = 0; k < LT; ++k) acc += sact[ln][k] * sW1[k * NC + c];
    g_z[node * NC + c] = 1.0f / (1.0f + __expf(-acc));
}

// ---------------------------------------------------------------- agg2 (pull, writes out directly)
__global__ void k_agg2(float* __restrict__ out, int nn) {
    const int t = blockIdx.x * blockDim.x + threadIdx.x;
    const int node = t >> 2;
    const int c = t & 3;
    if (node >= nn) return;
    int beg = g_row[node], end = g_row[node + 1];
    float ax = 0.f, ay = 0.f, az = 0.f, aw = 0.f;
    for (int i = beg; i < end; ++i) {
        int s = g_csr[i];
        float4 v = *reinterpret_cast<const float4*>(&g_z[s * NC + c * 4]);
        ax += v.x; ay += v.y; az += v.z; aw += v.w;
    }
    float4 o; o.x = ax; o.y = ay; o.z = az; o.w = aw;
    *reinterpret_cast<float4*>(&out[node * NC + c * 4]) = o;
}

// ---------------------------------------------------------------- launch
extern "C" void kernel_launch(void* const* d_in, const int* in_sizes, int n_in,
                              void* d_out, int out_size) {
    const float* nodes     = (const float*)d_in[0];
    const int*   senders   = (const int*)  d_in[1];
    const int*   receivers = (const int*)  d_in[2];
    const float* W0        = (const float*)d_in[3];
    const float* b0        = (const float*)d_in[4];
    const float* W1        = (const float*)d_in[5];
    const float* b1        = (const float*)d_in[6];
    float*       out       = (float*)d_out;

    const int nn = in_sizes[0] / DF;       // 100000
    const int ne = in_sizes[1];            // 1600000
    const int nb = (nn + 255) / 256;       // 391 scan blocks

    k_init<<<256, 256>>>(nn);
    k_degrees<<<(ne + 255) / 256, 256>>>(senders, receivers, ne);
    k_scan1<<<nb, 256>>>(nn);
    k_scan2<<<1, 512>>>(nb);
    k_scan3<<<nb, 256>>>(nn);
    k_bin<<<(ne + 255) / 256, 256>>>(senders, receivers, ne);
    k_gemm1<<<(nn + 63) / 64, 256>>>(nodes, W0, b0, nn);
    k_agg1l2<<<(nn + 15) / 16, 256>>>(W1, b1, nn);
    k_agg2<<<(nn * 4 + 255) / 256, 256>>>(out, nn);
}

// round 3
// speedup vs baseline: 1.9061x; 1.0442x over previous
#include <cuda_runtime.h>
#include <cuda_fp16.h>

// GCN_56882546868697 — 2-layer GCN, CSR pull + fp16 intermediates + f32x2 GEMM
// Inputs: nodes[f32 N*64], senders[i32 E], receivers[i32 E],
//         W0[f32 64*64], b0[f32 64], W1[f32 64*16], b1[f32 16]
// Output: out[f32 N*16]

#define NN 100000
#define NE 1600000
#define DF 64
#define LT 64
#define NC 16
#define NEG 0.01f

// ---- static scratch ----
__device__ __align__(16) __half g_h[NN * LT];  // layer-1 pre-agg, fp16 (128B/row)
__device__ __align__(16) __half g_z[NN * NC];  // layer-2 sigmoid acts, fp16 (32B/row)
__device__ int g_degs[NN];                     // out-degree (sender)
__device__ int g_degr[NN];                     // in-degree (receiver)
__device__ int g_beg[NN];                      // CSR segment start (unordered partition)
__device__ int g_cur[NN];                      // binning cursors
__device__ int g_csr[NE];                      // senders grouped by receiver
__device__ int g_total;                        // offset allocator

// ---------------------------------------------------------------- init
__global__ void k_init(int nn) {
    const int stride = gridDim.x * blockDim.x;
    int t0 = blockIdx.x * blockDim.x + threadIdx.x;
    for (int i = t0; i < nn; i += stride) { g_degs[i] = 0; g_degr[i] = 0; }
    if (t0 == 0) g_total = 0;
}

// ---------------------------------------------------------------- degrees (int4 vectorized)
__global__ void k_degrees(const int* __restrict__ senders,
                          const int* __restrict__ receivers, int ne) {
    int t = blockIdx.x * blockDim.x + threadIdx.x;
    int e0 = t * 4;
    if (e0 + 3 < ne) {
        int4 s = *reinterpret_cast<const int4*>(&senders[e0]);
        int4 r = *reinterpret_cast<const int4*>(&receivers[e0]);
        atomicAdd(&g_degs[s.x], 1); atomicAdd(&g_degs[s.y], 1);
        atomicAdd(&g_degs[s.z], 1); atomicAdd(&g_degs[s.w], 1);
        atomicAdd(&g_degr[r.x], 1); atomicAdd(&g_degr[r.y], 1);
        atomicAdd(&g_degr[r.z], 1); atomicAdd(&g_degr[r.w], 1);
    } else {
        for (int e = e0; e < ne; ++e) {
            atomicAdd(&g_degs[__ldg(&senders[e])], 1);
            atomicAdd(&g_degr[__ldg(&receivers[e])], 1);
        }
    }
}

// ---------------------------------------------------------------- segment offsets (no scan:
// ordering across nodes is irrelevant — each node only needs its own range)
__global__ void k_offsets(int nn) {
    int i = blockIdx.x * blockDim.x + threadIdx.x;
    if (i < nn) {
        int d = g_degr[i];
        int b = atomicAdd(&g_total, d);
        g_beg[i] = b;
        g_cur[i] = b;
    }
}

// ---------------------------------------------------------------- bin edges by receiver
__global__ void k_bin(const int* __restrict__ senders,
                      const int* __restrict__ receivers, int ne) {
    int t = blockIdx.x * blockDim.x + threadIdx.x;
    int e0 = t * 4;
    if (e0 + 3 < ne) {
        int4 s = *reinterpret_cast<const int4*>(&senders[e0]);
        int4 r = *reinterpret_cast<const int4*>(&receivers[e0]);
        g_csr[atomicAdd(&g_cur[r.x], 1)] = s.x;
        g_csr[atomicAdd(&g_cur[r.y], 1)] = s.y;
        g_csr[atomicAdd(&g_cur[r.z], 1)] = s.z;
        g_csr[atomicAdd(&g_cur[r.w], 1)] = s.w;
    } else {
        for (int e = e0; e < ne; ++e) {
            int r = __ldg(&receivers[e]);
            g_csr[atomicAdd(&g_cur[r], 1)] = __ldg(&senders[e]);
        }
    }
}

// ---------------------------------------------------------------- GEMM1 + sender norm -> fp16
// 64x64 tile/block, 256 thr, 4x4 register tile via packed fma.rn.f32x2 (FFMA2).
__global__ void k_gemm1(const float* __restrict__ nodes,
                        const float* __restrict__ W0,
                        const float* __restrict__ b0, int nn) {
    __shared__ __align__(16) float sW[DF * LT];      // [k][c]
    __shared__ float sx[64][DF + 1];                 // [r][k]
    const int tid = threadIdx.x;
    const int row0 = blockIdx.x * 64;

    for (int i = tid; i < DF * LT; i += 256) sW[i] = W0[i];
    for (int idx = tid; idx < 64 * 16; idx += 256) {
        int r = idx >> 4, k0 = (idx & 15) * 4;
        int grow = row0 + r;
        float4 v = (grow < nn)
            ? *reinterpret_cast<const float4*>(&nodes[grow * DF + k0])
            : make_float4(0.f, 0.f, 0.f, 0.f);
        sx[r][k0] = v.x; sx[r][k0 + 1] = v.y; sx[r][k0 + 2] = v.z; sx[r][k0 + 3] = v.w;
    }
    __syncthreads();

    const int ty = tid >> 4, tx = tid & 15;
    const int r0 = ty * 4, c0 = tx * 4;

    unsigned long long acc[4][2];
#pragma unroll
    for (int i = 0; i < 4; ++i) { acc[i][0] = 0ull; acc[i][1] = 0ull; }

#pragma unroll
    for (int k = 0; k < DF; ++k) {
        ulonglong2 b2 = *reinterpret_cast<const ulonglong2*>(&sW[k * LT + c0]);
#pragma unroll
        for (int i = 0; i < 4; ++i) {
            float a = sx[r0 + i][k];
            unsigned long long ap;
            asm("mov.b64 %0, {%1, %1};" : "=l"(ap) : "r"(__float_as_uint(a)));
            asm("fma.rn.f32x2 %0, %1, %2, %0;" : "+l"(acc[i][0]) : "l"(ap), "l"(b2.x));
            asm("fma.rn.f32x2 %0, %1, %2, %0;" : "+l"(acc[i][1]) : "l"(ap), "l"(b2.y));
        }
    }

    const float4 bias = *reinterpret_cast<const float4*>(&b0[c0]);
#pragma unroll
    for (int i = 0; i < 4; ++i) {
        int grow = row0 + r0 + i;
        if (grow < nn) {
            unsigned lo0, hi0, lo1, hi1;
            asm("mov.b64 {%0, %1}, %2;" : "=r"(lo0), "=r"(hi0) : "l"(acc[i][0]));
            asm("mov.b64 {%0, %1}, %2;" : "=r"(lo1), "=r"(hi1) : "l"(acc[i][1]));
            float s = rsqrtf(fmaxf((float)g_degs[grow], 1.0f));
            float ox = (__uint_as_float(lo0) + bias.x) * s;
            float oy = (__uint_as_float(hi0) + bias.y) * s;
            float oz = (__uint_as_float(lo1) + bias.z) * s;
            float ow = (__uint_as_float(hi1) + bias.w) * s;
            __half2 h0 = __floats2half2_rn(ox, oy);
            __half2 h1 = __floats2half2_rn(oz, ow);
            uint2 st;
            st.x = *reinterpret_cast<unsigned*>(&h0);
            st.y = *reinterpret_cast<unsigned*>(&h1);
            *reinterpret_cast<uint2*>(&g_h[grow * LT + c0]) = st;
        }
    }
}

// ---------------------------------------------------------------- agg1 + norm + leaky + GEMM2 + sigmoid
// 256 thr = 16 nodes x 16 lanes. Lane c pulls fp16 cols [4c,4c+4) over CSR,
// accumulates fp32, stages to smem; then 16x16 GEMM2 + sigmoid -> g_z (fp16).
__global__ void k_agg1l2(const float* __restrict__ W1,
                         const float* __restrict__ b1, int nn) {
    __shared__ float sW1[LT * NC];          // [k][c]
    __shared__ float sact[16][LT + 1];
    const int tid = threadIdx.x;
    for (int i = tid; i < LT * NC; i += 256) sW1[i] = W1[i];

    const int ln = tid >> 4;
    const int c  = tid & 15;
    const int node = blockIdx.x * 16 + ln;

    if (node < nn) {
        int beg = g_beg[node];
        int deg = g_degr[node];
        int end = beg + deg;
        float ax = 0.f, ay = 0.f, az = 0.f, aw = 0.f;
        for (int i = beg; i < end; ++i) {
            int s = g_csr[i];
            uint2 u = *reinterpret_cast<const uint2*>(&g_h[s * LT + c * 4]);
            float2 f0 = __half22float2(*reinterpret_cast<__half2*>(&u.x));
            float2 f1 = __half22float2(*reinterpret_cast<__half2*>(&u.y));
            ax += f0.x; ay += f0.y; az += f1.x; aw += f1.y;
        }
        float dr = rsqrtf(fmaxf((float)deg, 1.0f));
        ax *= dr; ay *= dr; az *= dr; aw *= dr;
        ax = (ax >= 0.f) ? ax : NEG * ax;
        ay = (ay >= 0.f) ? ay : NEG * ay;
        az = (az >= 0.f) ? az : NEG * az;
        aw = (aw >= 0.f) ? aw : NEG * aw;
        sact[ln][c * 4 + 0] = ax;
        sact[ln][c * 4 + 1] = ay;
        sact[ln][c * 4 + 2] = az;
        sact[ln][c * 4 + 3] = aw;
    }
    __syncthreads();

    if (node >= nn) return;
    float acc = __ldg(&b1[c]);
#pragma unroll
    for (int k = 0; k < LT; ++k) acc += sact[ln][k] * sW1[k * NC + c];
    float zz = 1.0f / (1.0f + __expf(-acc));
    g_z[node * NC + c] = __float2half_rn(zz);
}

// ---------------------------------------------------------------- agg2: pull fp16 z, write fp32 out
// 2 threads/node, each owns 8 columns (16B of fp16 per row).
__global__ void k_agg2(float* __restrict__ out, int nn) {
    const int t = blockIdx.x * blockDim.x + threadIdx.x;
    const int node = t >> 1;
    const int c = t & 1;
    if (node >= nn) return;
    int beg = g_beg[node];
    int end = beg + g_degr[node];
    float a[8] = {};
    for (int i = beg; i < end; ++i) {
        int s = g_csr[i];
        uint4 u = *reinterpret_cast<const uint4*>(&g_z[s * NC + c * 8]);
        float2 f0 = __half22float2(*reinterpret_cast<__half2*>(&u.x));
        float2 f1 = __half22float2(*reinterpret_cast<__half2*>(&u.y));
        float2 f2 = __half22float2(*reinterpret_cast<__half2*>(&u.z));
        float2 f3 = __half22float2(*reinterpret_cast<__half2*>(&u.w));
        a[0] += f0.x; a[1] += f0.y; a[2] += f1.x; a[3] += f1.y;
        a[4] += f2.x; a[5] += f2.y; a[6] += f3.x; a[7] += f3.y;
    }
    float4 o0 = make_float4(a[0], a[1], a[2], a[3]);
    float4 o1 = make_float4(a[4], a[5], a[6], a[7]);
    *reinterpret_cast<float4*>(&out[node * NC + c * 8])     = o0;
    *reinterpret_cast<float4*>(&out[node * NC + c * 8 + 4]) = o1;
}

// ---------------------------------------------------------------- launch
extern "C" void kernel_launch(void* const* d_in, const int* in_sizes, int n_in,
                              void* d_out, int out_size) {
    const float* nodes     = (const float*)d_in[0];
    const int*   senders   = (const int*)  d_in[1];
    const int*   receivers = (const int*)  d_in[2];
    const float* W0        = (const float*)d_in[3];
    const float* b0        = (const float*)d_in[4];
    const float* W1        = (const float*)d_in[5];
    const float* b1        = (const float*)d_in[6];
    float*       out       = (float*)d_out;

    const int nn = in_sizes[0] / DF;       // 100000
    const int ne = in_sizes[1];            // 1600000
    const int ne4 = (ne + 3) / 4;

    k_init<<<128, 256>>>(nn);
    k_degrees<<<(ne4 + 255) / 256, 256>>>(senders, receivers, ne);
    k_offsets<<<(nn + 255) / 256, 256>>>(nn);
    k_bin<<<(ne4 + 255) / 256, 256>>>(senders, receivers, ne);
    k_gemm1<<<(nn + 63) / 64, 256>>>(nodes, W0, b0, nn);
    k_agg1l2<<<(nn + 15) / 16, 256>>>(W1, b1, nn);
    k_agg2<<<(nn * 2 + 255) / 256, 256>>>(out, nn);
}

// round 4
// speedup vs baseline: 1.9336x; 1.0144x over previous
#include <cuda_runtime.h>
#include <cuda_fp16.h>

// GCN_56882546868697 — 2-layer GCN, CSR pull + fp16 intermediates + f32x2 GEMM
// R4: MLP-widened CSR build (8 edges/thread), 4x-unrolled aggregation loops.

#define NN 100000
#define NE 1600000
#define DF 64
#define LT 64
#define NC 16
#define NEG 0.01f

// ---- static scratch ----
__device__ __align__(16) __half g_h[NN * LT];  // layer-1 pre-agg, fp16 (128B/row)
__device__ __align__(16) __half g_z[NN * NC];  // layer-2 sigmoid acts, fp16 (32B/row)
__device__ int g_degs[NN];                     // out-degree (sender)
__device__ int g_degr[NN];                     // in-degree (receiver)
__device__ int g_beg[NN];                      // CSR segment start (unordered partition)
__device__ int g_cur[NN];                      // binning cursors
__device__ int g_csr[NE];                      // senders grouped by receiver
__device__ int g_total;                        // offset allocator

// ---------------------------------------------------------------- init
__global__ void k_init(int nn) {
    const int stride = gridDim.x * blockDim.x;
    int t0 = blockIdx.x * blockDim.x + threadIdx.x;
    for (int i = t0; i < nn; i += stride) { g_degs[i] = 0; g_degr[i] = 0; }
    if (t0 == 0) g_total = 0;
}

// ---------------------------------------------------------------- degrees: 8 edges/thread, pure RED
__global__ void k_degrees(const int* __restrict__ senders,
                          const int* __restrict__ receivers, int ne) {
    int t = blockIdx.x * blockDim.x + threadIdx.x;
    int e0 = t * 8;
    if (e0 + 7 < ne) {
        int4 s0 = *reinterpret_cast<const int4*>(&senders[e0]);
        int4 s1 = *reinterpret_cast<const int4*>(&senders[e0 + 4]);
        int4 r0 = *reinterpret_cast<const int4*>(&receivers[e0]);
        int4 r1 = *reinterpret_cast<const int4*>(&receivers[e0 + 4]);
        atomicAdd(&g_degs[s0.x], 1); atomicAdd(&g_degs[s0.y], 1);
        atomicAdd(&g_degs[s0.z], 1); atomicAdd(&g_degs[s0.w], 1);
        atomicAdd(&g_degs[s1.x], 1); atomicAdd(&g_degs[s1.y], 1);
        atomicAdd(&g_degs[s1.z], 1); atomicAdd(&g_degs[s1.w], 1);
        atomicAdd(&g_degr[r0.x], 1); atomicAdd(&g_degr[r0.y], 1);
        atomicAdd(&g_degr[r0.z], 1); atomicAdd(&g_degr[r0.w], 1);
        atomicAdd(&g_degr[r1.x], 1); atomicAdd(&g_degr[r1.y], 1);
        atomicAdd(&g_degr[r1.z], 1); atomicAdd(&g_degr[r1.w], 1);
    } else {
        for (int e = e0; e < ne; ++e) {
            atomicAdd(&g_degs[__ldg(&senders[e])], 1);
            atomicAdd(&g_degr[__ldg(&receivers[e])], 1);
        }
    }
}

// ---------------------------------------------------------------- segment offsets (unordered is fine)
__global__ void k_offsets(int nn) {
    int i = blockIdx.x * blockDim.x + threadIdx.x;
    if (i < nn) {
        int d = g_degr[i];
        int b = atomicAdd(&g_total, d);
        g_beg[i] = b;
        g_cur[i] = b;
    }
}

// ---------------------------------------------------------------- bin: 8 edges/thread,
// batched atomics then batched stores (maximize independent ops in flight)
__global__ void k_bin(const int* __restrict__ senders,
                      const int* __restrict__ receivers, int ne) {
    int t = blockIdx.x * blockDim.x + threadIdx.x;
    int e0 = t * 8;
    if (e0 + 7 < ne) {
        int4 s0 = *reinterpret_cast<const int4*>(&senders[e0]);
        int4 s1 = *reinterpret_cast<const int4*>(&senders[e0 + 4]);
        int4 r0 = *reinterpret_cast<const int4*>(&receivers[e0]);
        int4 r1 = *reinterpret_cast<const int4*>(&receivers[e0 + 4]);
        int p0 = atomicAdd(&g_cur[r0.x], 1);
        int p1 = atomicAdd(&g_cur[r0.y], 1);
        int p2 = atomicAdd(&g_cur[r0.z], 1);
        int p3 = atomicAdd(&g_cur[r0.w], 1);
        int p4 = atomicAdd(&g_cur[r1.x], 1);
        int p5 = atomicAdd(&g_cur[r1.y], 1);
        int p6 = atomicAdd(&g_cur[r1.z], 1);
        int p7 = atomicAdd(&g_cur[r1.w], 1);
        g_csr[p0] = s0.x; g_csr[p1] = s0.y; g_csr[p2] = s0.z; g_csr[p3] = s0.w;
        g_csr[p4] = s1.x; g_csr[p5] = s1.y; g_csr[p6] = s1.z; g_csr[p7] = s1.w;
    } else {
        for (int e = e0; e < ne; ++e) {
            int r = __ldg(&receivers[e]);
            g_csr[atomicAdd(&g_cur[r], 1)] = __ldg(&senders[e]);
        }
    }
}

// ---------------------------------------------------------------- GEMM1 + sender norm -> fp16
__global__ void k_gemm1(const float* __restrict__ nodes,
                        const float* __restrict__ W0,
                        const float* __restrict__ b0, int nn) {
    __shared__ __align__(16) float sW[DF * LT];      // [k][c]
    __shared__ float sx[64][DF + 1];                 // [r][k]
    const int tid = threadIdx.x;
    const int row0 = blockIdx.x * 64;

    for (int i = tid; i < DF * LT; i += 256) sW[i] = W0[i];
    for (int idx = tid; idx < 64 * 16; idx += 256) {
        int r = idx >> 4, k0 = (idx & 15) * 4;
        int grow = row0 + r;
        float4 v = (grow < nn)
            ? *reinterpret_cast<const float4*>(&nodes[grow * DF + k0])
            : make_float4(0.f, 0.f, 0.f, 0.f);
        sx[r][k0] = v.x; sx[r][k0 + 1] = v.y; sx[r][k0 + 2] = v.z; sx[r][k0 + 3] = v.w;
    }
    __syncthreads();

    const int ty = tid >> 4, tx = tid & 15;
    const int r0 = ty * 4, c0 = tx * 4;

    unsigned long long acc[4][2];
#pragma unroll
    for (int i = 0; i < 4; ++i) { acc[i][0] = 0ull; acc[i][1] = 0ull; }

#pragma unroll
    for (int k = 0; k < DF; ++k) {
        ulonglong2 b2 = *reinterpret_cast<const ulonglong2*>(&sW[k * LT + c0]);
#pragma unroll
        for (int i = 0; i < 4; ++i) {
            float a = sx[r0 + i][k];
            unsigned long long ap;
            asm("mov.b64 %0, {%1, %1};" : "=l"(ap) : "r"(__float_as_uint(a)));
            asm("fma.rn.f32x2 %0, %1, %2, %0;" : "+l"(acc[i][0]) : "l"(ap), "l"(b2.x));
            asm("fma.rn.f32x2 %0, %1, %2, %0;" : "+l"(acc[i][1]) : "l"(ap), "l"(b2.y));
        }
    }

    const float4 bias = *reinterpret_cast<const float4*>(&b0[c0]);
#pragma unroll
    for (int i = 0; i < 4; ++i) {
        int grow = row0 + r0 + i;
        if (grow < nn) {
            unsigned lo0, hi0, lo1, hi1;
            asm("mov.b64 {%0, %1}, %2;" : "=r"(lo0), "=r"(hi0) : "l"(acc[i][0]));
            asm("mov.b64 {%0, %1}, %2;" : "=r"(lo1), "=r"(hi1) : "l"(acc[i][1]));
            float s = rsqrtf(fmaxf((float)g_degs[grow], 1.0f));
            float ox = (__uint_as_float(lo0) + bias.x) * s;
            float oy = (__uint_as_float(hi0) + bias.y) * s;
            float oz = (__uint_as_float(lo1) + bias.z) * s;
            float ow = (__uint_as_float(hi1) + bias.w) * s;
            __half2 h0 = __floats2half2_rn(ox, oy);
            __half2 h1 = __floats2half2_rn(oz, ow);
            uint2 st;
            st.x = *reinterpret_cast<unsigned*>(&h0);
            st.y = *reinterpret_cast<unsigned*>(&h1);
            *reinterpret_cast<uint2*>(&g_h[grow * LT + c0]) = st;
        }
    }
}

// ---------------------------------------------------------------- agg1 + norm + leaky + GEMM2 + sigmoid
// 256 thr = 16 nodes x 16 lanes; neighbor loop unrolled 4x for MLP.
__global__ void k_agg1l2(const float* __restrict__ W1,
                         const float* __restrict__ b1, int nn) {
    __shared__ float sW1[LT * NC];          // [k][c]
    __shared__ float sact[16][LT + 1];
    const int tid = threadIdx.x;
    for (int i = tid; i < LT * NC; i += 256) sW1[i] = W1[i];

    const int ln = tid >> 4;
    const int c  = tid & 15;
    const int node = blockIdx.x * 16 + ln;

    if (node < nn) {
        int beg = g_beg[node];
        int deg = g_degr[node];
        int end = beg + deg;
        float ax = 0.f, ay = 0.f, az = 0.f, aw = 0.f;
        int i = beg;
        for (; i + 4 <= end; i += 4) {
            int s0 = __ldg(&g_csr[i]);
            int s1 = __ldg(&g_csr[i + 1]);
            int s2 = __ldg(&g_csr[i + 2]);
            int s3 = __ldg(&g_csr[i + 3]);
            uint2 u0 = *reinterpret_cast<const uint2*>(&g_h[s0 * LT + c * 4]);
            uint2 u1 = *reinterpret_cast<const uint2*>(&g_h[s1 * LT + c * 4]);
            uint2 u2 = *reinterpret_cast<const uint2*>(&g_h[s2 * LT + c * 4]);
            uint2 u3 = *reinterpret_cast<const uint2*>(&g_h[s3 * LT + c * 4]);
            float2 a0 = __half22float2(*reinterpret_cast<__half2*>(&u0.x));
            float2 b0_ = __half22float2(*reinterpret_cast<__half2*>(&u0.y));
            float2 a1 = __half22float2(*reinterpret_cast<__half2*>(&u1.x));
            float2 b1_ = __half22float2(*reinterpret_cast<__half2*>(&u1.y));
            float2 a2 = __half22float2(*reinterpret_cast<__half2*>(&u2.x));
            float2 b2_ = __half22float2(*reinterpret_cast<__half2*>(&u2.y));
            float2 a3 = __half22float2(*reinterpret_cast<__half2*>(&u3.x));
            float2 b3_ = __half22float2(*reinterpret_cast<__half2*>(&u3.y));
            ax += a0.x + a1.x + a2.x + a3.x;
            ay += a0.y + a1.y + a2.y + a3.y;
            az += b0_.x + b1_.x + b2_.x + b3_.x;
            aw += b0_.y + b1_.y + b2_.y + b3_.y;
        }
        for (; i < end; ++i) {
            int s = __ldg(&g_csr[i]);
            uint2 u = *reinterpret_cast<const uint2*>(&g_h[s * LT + c * 4]);
            float2 f0 = __half22float2(*reinterpret_cast<__half2*>(&u.x));
            float2 f1 = __half22float2(*reinterpret_cast<__half2*>(&u.y));
            ax += f0.x; ay += f0.y; az += f1.x; aw += f1.y;
        }
        float dr = rsqrtf(fmaxf((float)deg, 1.0f));
        ax *= dr; ay *= dr; az *= dr; aw *= dr;
        ax = (ax >= 0.f) ? ax : NEG * ax;
        ay = (ay >= 0.f) ? ay : NEG * ay;
        az = (az >= 0.f) ? az : NEG * az;
        aw = (aw >= 0.f) ? aw : NEG * aw;
        sact[ln][c * 4 + 0] = ax;
        sact[ln][c * 4 + 1] = ay;
        sact[ln][c * 4 + 2] = az;
        sact[ln][c * 4 + 3] = aw;
    }
    __syncthreads();

    if (node >= nn) return;
    float acc = __ldg(&b1[c]);
#pragma unroll
    for (int k = 0; k < LT; ++k) acc += sact[ln][k] * sW1[k * NC + c];
    float zz = 1.0f / (1.0f + __expf(-acc));
    g_z[node * NC + c] = __float2half_rn(zz);
}

// ---------------------------------------------------------------- agg2: pull fp16 z, write fp32 out
// 2 threads/node, each owns 8 columns; loop unrolled 2x (uint4 = 16B per lane).
__global__ void k_agg2(float* __restrict__ out, int nn) {
    const int t = blockIdx.x * blockDim.x + threadIdx.x;
    const int node = t >> 1;
    const int c = t & 1;
    if (node >= nn) return;
    int beg = g_beg[node];
    int end = beg + g_degr[node];
    float a[8] = {};
    int i = beg;
    for (; i + 2 <= end; i += 2) {
        int s0 = __ldg(&g_csr[i]);
        int s1 = __ldg(&g_csr[i + 1]);
        uint4 u0 = *reinterpret_cast<const uint4*>(&g_z[s0 * NC + c * 8]);
        uint4 u1 = *reinterpret_cast<const uint4*>(&g_z[s1 * NC + c * 8]);
        float2 f;
        f = __half22float2(*reinterpret_cast<__half2*>(&u0.x)); a[0] += f.x; a[1] += f.y;
        f = __half22float2(*reinterpret_cast<__half2*>(&u0.y)); a[2] += f.x; a[3] += f.y;
        f = __half22float2(*reinterpret_cast<__half2*>(&u0.z)); a[4] += f.x; a[5] += f.y;
        f = __half22float2(*reinterpret_cast<__half2*>(&u0.w)); a[6] += f.x; a[7] += f.y;
        f = __half22float2(*reinterpret_cast<__half2*>(&u1.x)); a[0] += f.x; a[1] += f.y;
        f = __half22float2(*reinterpret_cast<__half2*>(&u1.y)); a[2] += f.x; a[3] += f.y;
        f = __half22float2(*reinterpret_cast<__half2*>(&u1.z)); a[4] += f.x; a[5] += f.y;
        f = __half22float2(*reinterpret_cast<__half2*>(&u1.w)); a[6] += f.x; a[7] += f.y;
    }
    for (; i < end; ++i) {
        int s = __ldg(&g_csr[i]);
        uint4 u = *reinterpret_cast<const uint4*>(&g_z[s * NC + c * 8]);
        float2 f;
        f = __half22float2(*reinterpret_cast<__half2*>(&u.x)); a[0] += f.x; a[1] += f.y;
        f = __half22float2(*reinterpret_cast<__half2*>(&u.y)); a[2] += f.x; a[3] += f.y;
        f = __half22float2(*reinterpret_cast<__half2*>(&u.z)); a[4] += f.x; a[5] += f.y;
        f = __half22float2(*reinterpret_cast<__half2*>(&u.w)); a[6] += f.x; a[7] += f.y;
    }
    float4 o0 = make_float4(a[0], a[1], a[2], a[3]);
    float4 o1 = make_float4(a[4], a[5], a[6], a[7]);
    *reinterpret_cast<float4*>(&out[node * NC + c * 8])     = o0;
    *reinterpret_cast<float4*>(&out[node * NC + c * 8 + 4]) = o1;
}

// ---------------------------------------------------------------- launch
extern "C" void kernel_launch(void* const* d_in, const int* in_sizes, int n_in,
                              void* d_out, int out_size) {
    const float* nodes     = (const float*)d_in[0];
    const int*   senders   = (const int*)  d_in[1];
    const int*   receivers = (const int*)  d_in[2];
    const float* W0        = (const float*)d_in[3];
    const float* b0        = (const float*)d_in[4];
    const float* W1        = (const float*)d_in[5];
    const float* b1        = (const float*)d_in[6];
    float*       out       = (float*)d_out;

    const int nn = in_sizes[0] / DF;       // 100000
    const int ne = in_sizes[1];            // 1600000
    const int ne8 = (ne + 7) / 8;

    k_init<<<128, 256>>>(nn);
    k_degrees<<<(ne8 + 255) / 256, 256>>>(senders, receivers, ne);
    k_offsets<<<(nn + 255) / 256, 256>>>(nn);
    k_bin<<<(ne8 + 255) / 256, 256>>>(senders, receivers, ne);
    k_gemm1<<<(nn + 63) / 64, 256>>>(nodes, W0, b0, nn);
    k_agg1l2<<<(nn + 15) / 16, 256>>>(W1, b1, nn);
    k_agg2<<<(nn * 2 + 255) / 256, 256>>>(out, nn);
}

// round 5
// speedup vs baseline: 2.0625x; 1.0667x over previous
#include <cuda_runtime.h>
#include <cuda_fp16.h>

// GCN_56882546868697 — 2-layer GCN, CSR pull + fp16 intermediates + f32x2 GEMM
// R5: fork/join parallel graph (CSR-build branch || deg_s+GEMM1 branch),
//     warp-aggregated offset allocation, 4 edges/thread atomic kernels.

#define NN 100000
#define NE 1600000
#define DF 64
#define LT 64
#define NC 16
#define NEG 0.01f

// ---- static scratch ----
__device__ __align__(16) __half g_h[NN * LT];  // layer-1 pre-agg, fp16 (128B/row)
__device__ __align__(16) __half g_z[NN * NC];  // layer-2 sigmoid acts, fp16 (32B/row)
__device__ int g_degs[NN];                     // out-degree (sender)
__device__ int g_degr[NN];                     // in-degree (receiver)
__device__ int g_beg[NN];                      // CSR segment start (unordered partition)
__device__ int g_cur[NN];                      // binning cursors
__device__ int g_csr[NE];                      // senders grouped by receiver
__device__ int g_total;                        // offset allocator

// ---------------------------------------------------------------- init (both branches' state)
__global__ void k_init(int nn) {
    const int stride = gridDim.x * blockDim.x;
    int t0 = blockIdx.x * blockDim.x + threadIdx.x;
    for (int i = t0; i < nn; i += stride) { g_degs[i] = 0; g_degr[i] = 0; }
    if (t0 == 0) g_total = 0;
}

// ---------------------------------------------------------------- sender-degree histogram (branch B)
__global__ void k_hist_s(const int* __restrict__ senders, int ne) {
    int t = blockIdx.x * blockDim.x + threadIdx.x;
    int e0 = t * 4;
    if (e0 + 3 < ne) {
        int4 s = *reinterpret_cast<const int4*>(&senders[e0]);
        atomicAdd(&g_degs[s.x], 1); atomicAdd(&g_degs[s.y], 1);
        atomicAdd(&g_degs[s.z], 1); atomicAdd(&g_degs[s.w], 1);
    } else {
        for (int e = e0; e < ne; ++e) atomicAdd(&g_degs[__ldg(&senders[e])], 1);
    }
}

// ---------------------------------------------------------------- receiver-degree histogram (branch A)
__global__ void k_hist_r(const int* __restrict__ receivers, int ne) {
    int t = blockIdx.x * blockDim.x + threadIdx.x;
    int e0 = t * 4;
    if (e0 + 3 < ne) {
        int4 r = *reinterpret_cast<const int4*>(&receivers[e0]);
        atomicAdd(&g_degr[r.x], 1); atomicAdd(&g_degr[r.y], 1);
        atomicAdd(&g_degr[r.z], 1); atomicAdd(&g_degr[r.w], 1);
    } else {
        for (int e = e0; e < ne; ++e) atomicAdd(&g_degr[__ldg(&receivers[e])], 1);
    }
}

// ---------------------------------------------------------------- segment offsets
// warp-scan + 1 atomic per warp (ordering across nodes irrelevant)
__global__ void k_offsets(int nn) {
    int i = blockIdx.x * blockDim.x + threadIdx.x;
    int lane = threadIdx.x & 31;
    int d = (i < nn) ? g_degr[i] : 0;
    int pre = d;
#pragma unroll
    for (int o = 1; o < 32; o <<= 1) {
        int v = __shfl_up_sync(0xffffffffu, pre, o);
        if (lane >= o) pre += v;
    }
    int excl = pre - d;
    int wsum = __shfl_sync(0xffffffffu, pre, 31);
    int base = 0;
    if (lane == 0) base = atomicAdd(&g_total, wsum);
    base = __shfl_sync(0xffffffffu, base, 0);
    if (i < nn) {
        int b = base + excl;
        g_beg[i] = b;
        g_cur[i] = b;
    }
}

// ---------------------------------------------------------------- bin edges by receiver
__global__ void k_bin(const int* __restrict__ senders,
                      const int* __restrict__ receivers, int ne) {
    int t = blockIdx.x * blockDim.x + threadIdx.x;
    int e0 = t * 4;
    if (e0 + 3 < ne) {
        int4 s = *reinterpret_cast<const int4*>(&senders[e0]);
        int4 r = *reinterpret_cast<const int4*>(&receivers[e0]);
        int p0 = atomicAdd(&g_cur[r.x], 1);
        int p1 = atomicAdd(&g_cur[r.y], 1);
        int p2 = atomicAdd(&g_cur[r.z], 1);
        int p3 = atomicAdd(&g_cur[r.w], 1);
        g_csr[p0] = s.x; g_csr[p1] = s.y; g_csr[p2] = s.z; g_csr[p3] = s.w;
    } else {
        for (int e = e0; e < ne; ++e) {
            int r = __ldg(&receivers[e]);
            g_csr[atomicAdd(&g_cur[r], 1)] = __ldg(&senders[e]);
        }
    }
}

// ---------------------------------------------------------------- GEMM1 + sender norm -> fp16
__global__ void k_gemm1(const float* __restrict__ nodes,
                        const float* __restrict__ W0,
                        const float* __restrict__ b0, int nn) {
    __shared__ __align__(16) float sW[DF * LT];      // [k][c]
    __shared__ float sx[64][DF + 1];                 // [r][k]
    const int tid = threadIdx.x;
    const int row0 = blockIdx.x * 64;

    for (int i = tid; i < DF * LT; i += 256) sW[i] = W0[i];
    for (int idx = tid; idx < 64 * 16; idx += 256) {
        int r = idx >> 4, k0 = (idx & 15) * 4;
        int grow = row0 + r;
        float4 v = (grow < nn)
            ? *reinterpret_cast<const float4*>(&nodes[grow * DF + k0])
            : make_float4(0.f, 0.f, 0.f, 0.f);
        sx[r][k0] = v.x; sx[r][k0 + 1] = v.y; sx[r][k0 + 2] = v.z; sx[r][k0 + 3] = v.w;
    }
    __syncthreads();

    const int ty = tid >> 4, tx = tid & 15;
    const int r0 = ty * 4, c0 = tx * 4;

    unsigned long long acc[4][2];
#pragma unroll
    for (int i = 0; i < 4; ++i) { acc[i][0] = 0ull; acc[i][1] = 0ull; }

#pragma unroll
    for (int k = 0; k < DF; ++k) {
        ulonglong2 b2 = *reinterpret_cast<const ulonglong2*>(&sW[k * LT + c0]);
#pragma unroll
        for (int i = 0; i < 4; ++i) {
            float a = sx[r0 + i][k];
            unsigned long long ap;
            asm("mov.b64 %0, {%1, %1};" : "=l"(ap) : "r"(__float_as_uint(a)));
            asm("fma.rn.f32x2 %0, %1, %2, %0;" : "+l"(acc[i][0]) : "l"(ap), "l"(b2.x));
            asm("fma.rn.f32x2 %0, %1, %2, %0;" : "+l"(acc[i][1]) : "l"(ap), "l"(b2.y));
        }
    }

    const float4 bias = *reinterpret_cast<const float4*>(&b0[c0]);
#pragma unroll
    for (int i = 0; i < 4; ++i) {
        int grow = row0 + r0 + i;
        if (grow < nn) {
            unsigned lo0, hi0, lo1, hi1;
            asm("mov.b64 {%0, %1}, %2;" : "=r"(lo0), "=r"(hi0) : "l"(acc[i][0]));
            asm("mov.b64 {%0, %1}, %2;" : "=r"(lo1), "=r"(hi1) : "l"(acc[i][1]));
            float s = rsqrtf(fmaxf((float)g_degs[grow], 1.0f));
            float ox = (__uint_as_float(lo0) + bias.x) * s;
            float oy = (__uint_as_float(hi0) + bias.y) * s;
            float oz = (__uint_as_float(lo1) + bias.z) * s;
            float ow = (__uint_as_float(hi1) + bias.w) * s;
            __half2 h0 = __floats2half2_rn(ox, oy);
            __half2 h1 = __floats2half2_rn(oz, ow);
            uint2 st;
            st.x = *reinterpret_cast<unsigned*>(&h0);
            st.y = *reinterpret_cast<unsigned*>(&h1);
            *reinterpret_cast<uint2*>(&g_h[grow * LT + c0]) = st;
        }
    }
}

// ---------------------------------------------------------------- agg1 + norm + leaky + GEMM2 + sigmoid
__global__ void k_agg1l2(const float* __restrict__ W1,
                         const float* __restrict__ b1, int nn) {
    __shared__ float sW1[LT * NC];          // [k][c]
    __shared__ float sact[16][LT + 1];
    const int tid = threadIdx.x;
    for (int i = tid; i < LT * NC; i += 256) sW1[i] = W1[i];

    const int ln = tid >> 4;
    const int c  = tid & 15;
    const int node = blockIdx.x * 16 + ln;

    if (node < nn) {
        int beg = g_beg[node];
        int deg = g_degr[node];
        int end = beg + deg;
        float ax = 0.f, ay = 0.f, az = 0.f, aw = 0.f;
        int i = beg;
        for (; i + 4 <= end; i += 4) {
            int s0 = __ldg(&g_csr[i]);
            int s1 = __ldg(&g_csr[i + 1]);
            int s2 = __ldg(&g_csr[i + 2]);
            int s3 = __ldg(&g_csr[i + 3]);
            uint2 u0 = *reinterpret_cast<const uint2*>(&g_h[s0 * LT + c * 4]);
            uint2 u1 = *reinterpret_cast<const uint2*>(&g_h[s1 * LT + c * 4]);
            uint2 u2 = *reinterpret_cast<const uint2*>(&g_h[s2 * LT + c * 4]);
            uint2 u3 = *reinterpret_cast<const uint2*>(&g_h[s3 * LT + c * 4]);
            float2 a0 = __half22float2(*reinterpret_cast<__half2*>(&u0.x));
            float2 b0_ = __half22float2(*reinterpret_cast<__half2*>(&u0.y));
            float2 a1 = __half22float2(*reinterpret_cast<__half2*>(&u1.x));
            float2 b1_ = __half22float2(*reinterpret_cast<__half2*>(&u1.y));
            float2 a2 = __half22float2(*reinterpret_cast<__half2*>(&u2.x));
            float2 b2_ = __half22float2(*reinterpret_cast<__half2*>(&u2.y));
            float2 a3 = __half22float2(*reinterpret_cast<__half2*>(&u3.x));
            float2 b3_ = __half22float2(*reinterpret_cast<__half2*>(&u3.y));
            ax += a0.x + a1.x + a2.x + a3.x;
            ay += a0.y + a1.y + a2.y + a3.y;
            az += b0_.x + b1_.x + b2_.x + b3_.x;
            aw += b0_.y + b1_.y + b2_.y + b3_.y;
        }
        for (; i < end; ++i) {
            int s = __ldg(&g_csr[i]);
            uint2 u = *reinterpret_cast<const uint2*>(&g_h[s * LT + c * 4]);
            float2 f0 = __half22float2(*reinterpret_cast<__half2*>(&u.x));
            float2 f1 = __half22float2(*reinterpret_cast<__half2*>(&u.y));
            ax += f0.x; ay += f0.y; az += f1.x; aw += f1.y;
        }
        float dr = rsqrtf(fmaxf((float)deg, 1.0f));
        ax *= dr; ay *= dr; az *= dr; aw *= dr;
        ax = (ax >= 0.f) ? ax : NEG * ax;
        ay = (ay >= 0.f) ? ay : NEG * ay;
        az = (az >= 0.f) ? az : NEG * az;
        aw = (aw >= 0.f) ? aw : NEG * aw;
        sact[ln][c * 4 + 0] = ax;
        sact[ln][c * 4 + 1] = ay;
        sact[ln][c * 4 + 2] = az;
        sact[ln][c * 4 + 3] = aw;
    }
    __syncthreads();

    if (node >= nn) return;
    float acc = __ldg(&b1[c]);
#pragma unroll
    for (int k = 0; k < LT; ++k) acc += sact[ln][k] * sW1[k * NC + c];
    float zz = 1.0f / (1.0f + __expf(-acc));
    g_z[node * NC + c] = __float2half_rn(zz);
}

// ---------------------------------------------------------------- agg2: pull fp16 z, write fp32 out
__global__ void k_agg2(float* __restrict__ out, int nn) {
    const int t = blockIdx.x * blockDim.x + threadIdx.x;
    const int node = t >> 1;
    const int c = t & 1;
    if (node >= nn) return;
    int beg = g_beg[node];
    int end = beg + g_degr[node];
    float a[8] = {};
    int i = beg;
    for (; i + 2 <= end; i += 2) {
        int s0 = __ldg(&g_csr[i]);
        int s1 = __ldg(&g_csr[i + 1]);
        uint4 u0 = *reinterpret_cast<const uint4*>(&g_z[s0 * NC + c * 8]);
        uint4 u1 = *reinterpret_cast<const uint4*>(&g_z[s1 * NC + c * 8]);
        float2 f;
        f = __half22float2(*reinterpret_cast<__half2*>(&u0.x)); a[0] += f.x; a[1] += f.y;
        f = __half22float2(*reinterpret_cast<__half2*>(&u0.y)); a[2] += f.x; a[3] += f.y;
        f = __half22float2(*reinterpret_cast<__half2*>(&u0.z)); a[4] += f.x; a[5] += f.y;
        f = __half22float2(*reinterpret_cast<__half2*>(&u0.w)); a[6] += f.x; a[7] += f.y;
        f = __half22float2(*reinterpret_cast<__half2*>(&u1.x)); a[0] += f.x; a[1] += f.y;
        f = __half22float2(*reinterpret_cast<__half2*>(&u1.y)); a[2] += f.x; a[3] += f.y;
        f = __half22float2(*reinterpret_cast<__half2*>(&u1.z)); a[4] += f.x; a[5] += f.y;
        f = __half22float2(*reinterpret_cast<__half2*>(&u1.w)); a[6] += f.x; a[7] += f.y;
    }
    for (; i < end; ++i) {
        int s = __ldg(&g_csr[i]);
        uint4 u = *reinterpret_cast<const uint4*>(&g_z[s * NC + c * 8]);
        float2 f;
        f = __half22float2(*reinterpret_cast<__half2*>(&u.x)); a[0] += f.x; a[1] += f.y;
        f = __half22float2(*reinterpret_cast<__half2*>(&u.y)); a[2] += f.x; a[3] += f.y;
        f = __half22float2(*reinterpret_cast<__half2*>(&u.z)); a[4] += f.x; a[5] += f.y;
        f = __half22float2(*reinterpret_cast<__half2*>(&u.w)); a[6] += f.x; a[7] += f.y;
    }
    float4 o0 = make_float4(a[0], a[1], a[2], a[3]);
    float4 o1 = make_float4(a[4], a[5], a[6], a[7]);
    *reinterpret_cast<float4*>(&out[node * NC + c * 8])     = o0;
    *reinterpret_cast<float4*>(&out[node * NC + c * 8 + 4]) = o1;
}

// ---------------------------------------------------------------- launch (fork/join graph)
extern "C" void kernel_launch(void* const* d_in, const int* in_sizes, int n_in,
                              void* d_out, int out_size) {
    const float* nodes     = (const float*)d_in[0];
    const int*   senders   = (const int*)  d_in[1];
    const int*   receivers = (const int*)  d_in[2];
    const float* W0        = (const float*)d_in[3];
    const float* b0        = (const float*)d_in[4];
    const float* W1        = (const float*)d_in[5];
    const float* b1        = (const float*)d_in[6];
    float*       out       = (float*)d_out;

    const int nn = in_sizes[0] / DF;       // 100000
    const int ne = in_sizes[1];            // 1600000
    const int ne4 = (ne + 3) / 4;
    const int eg  = (ne4 + 255) / 256;     // grid for 4-edges/thread kernels

    // One-time side stream + events (same work every call; no device memory).
    static cudaStream_t s2 = 0;
    static cudaEvent_t evFork = 0, evJoin = 0;
    if (!s2) {
        cudaStreamCreateWithFlags(&s2, cudaStreamNonBlocking);
        cudaEventCreateWithFlags(&evFork, cudaEventDisableTiming);
        cudaEventCreateWithFlags(&evJoin, cudaEventDisableTiming);
    }

    // stream 0: init (zeroes state used by both branches)
    k_init<<<128, 256>>>(nn);
    cudaEventRecord(evFork, 0);

    // branch B (stream s2): deg_s -> GEMM1 (compute-heavy; overlaps branch A's atomics)
    cudaStreamWaitEvent(s2, evFork, 0);
    k_hist_s<<<eg, 256, 0, s2>>>(senders, ne);
    k_gemm1<<<(nn + 63) / 64, 256, 0, s2>>>(nodes, W0, b0, nn);
    cudaEventRecord(evJoin, s2);

    // branch A (stream 0): deg_r -> offsets -> bin (latency/atomic-bound)
    k_hist_r<<<eg, 256>>>(receivers, ne);
    k_offsets<<<(nn + 255) / 256, 256>>>(nn);
    k_bin<<<eg, 256>>>(senders, receivers, ne);

    // join: aggregation needs both CSR (A) and g_h (B)
    cudaStreamWaitEvent(0, evJoin, 0);
    k_agg1l2<<<(nn + 15) / 16, 256>>>(W1, b1, nn);
    k_agg2<<<(nn * 2 + 255) / 256, 256>>>(out, nn);
}